// round 16
// baseline (speedup 1.0000x reference)
#include <cuda_runtime.h>
#include <math.h>
#include <stdint.h>

#define LSEQ 1024
#define DM   1024
#define DI   2048
#define DS   16
#define DTR  64

// ---------------- scratch ----------------
__device__ __align__(16) float g_xz[2][LSEQ][2*DI];
__device__ __align__(16) float g_u [2][LSEQ][DI];
__device__ __align__(16) float g_xdbl_part[2][16][LSEQ][96];
__device__ __align__(16) float g_xdbl[2][LSEQ][96];
__device__ __align__(16) float g_delta[2][LSEQ][DI];
__device__ __align__(16) float g_cat[LSEQ][2*DM];
__device__ __align__(16) float g_opart[2][2][LSEQ][DM];
__device__ __align__(16) float g_fpart[4][LSEQ][DM];

// fused tf32 hi/lo operands (tensor half of in_proj)
__device__ __align__(16) float g_xiA[2][LSEQ * 2 * DM];
__device__ __align__(16) float g_iwA[2][2 * DI * 2 * DM];   // only n<2048 filled

// k-major fp32 operands
__device__ __align__(16) float g_xT   [DM][LSEQ];
__device__ __align__(16) float g_xrevT[DM][LSEQ];
__device__ __align__(16) float g_inwT [2][DM * 2 * DI];     // in_w^T [1024][4096]
__device__ __align__(16) float g_outwT[2][DI * DM];
__device__ __align__(16) float g_pwT  [2 * DM * DM];
__device__ __align__(16) float g_dtwT [2][DTR * DI];
__device__ __align__(16) float g_xdT  [2][DTR][LSEQ];
__device__ __align__(16) float g_y2T  [2][DI][LSEQ];
__device__ __align__(16) float g_catT [2 * DM][LSEQ];

__device__ __forceinline__ float sigmoid_f(float x) {
    return __fdividef(1.f, 1.f + __expf(-x));
}
__device__ __forceinline__ float softplus_f(float x) {
    return (x > 20.f) ? x : log1pf(__expf(x));
}

typedef unsigned long long u64t;
__device__ __forceinline__ u64t pack2(float lo, float hi) {
    u64t r;
    asm("mov.b64 %0, {%1, %2};" : "=l"(r) : "r"(__float_as_uint(lo)), "r"(__float_as_uint(hi)));
    return r;
}
__device__ __forceinline__ void unpack2(u64t v, float& lo, float& hi) {
    uint32_t a, b;
    asm("mov.b64 {%0, %1}, %2;" : "=r"(a), "=r"(b) : "l"(v));
    lo = __uint_as_float(a);
    hi = __uint_as_float(b);
}
#define FFMA2(d, a, b, c) \
    asm("fma.rn.f32x2 %0, %1, %2, %3;" : "=l"(d) : "l"(a), "l"(b), "l"(c))

__device__ __forceinline__ float tf32_round(float v) {
    uint32_t r;
    asm("cvt.rna.tf32.f32 %0, %1;" : "=r"(r) : "f"(v));
    return __uint_as_float(r);
}
#define MMA_TF32(c, a0, a1, a2, a3, b0, b1) \
    asm volatile("mma.sync.aligned.m16n8k8.row.col.f32.tf32.tf32.f32 " \
        "{%0,%1,%2,%3}, {%4,%5,%6,%7}, {%8,%9}, {%0,%1,%2,%3};" \
        : "+f"((c)[0]), "+f"((c)[1]), "+f"((c)[2]), "+f"((c)[3]) \
        : "r"(a0), "r"(a1), "r"(a2), "r"(a3), "r"(b0), "r"(b1))

__device__ __forceinline__ uint32_t smem_u32(const void* p) {
    return (uint32_t)__cvta_generic_to_shared(p);
}
#define CP_ASYNC16(dst, src) \
    asm volatile("cp.async.cg.shared.global [%0], [%1], 16;" :: "r"(dst), "l"(src) : "memory")
#define CP_COMMIT() asm volatile("cp.async.commit_group;" ::: "memory")
#define CP_WAIT1()  asm volatile("cp.async.wait_group 1;" ::: "memory")
#define CP_WAIT0()  asm volatile("cp.async.wait_group 0;" ::: "memory")

// ---------------- prep: x -> fused tf32 hi/lo (fw + reversed) ----------------
__global__ void __launch_bounds__(256)
prep_x_kernel(const float* __restrict__ x)
{
    int gid = blockIdx.x * 256 + threadIdx.x;     // LSEQ * 128
    int m  = gid >> 7;
    int g  = gid & 127;
    const float* src = x + (size_t)m * DM + g * 8;
    float v[8], h[8], l[8];
#pragma unroll
    for (int i = 0; i < 8; i++) v[i] = src[i];
#pragma unroll
    for (int i = 0; i < 8; i++) {
        h[i] = tf32_round(v[i]);
        l[i] = tf32_round(v[i] - h[i]);
    }
    float4 c0 = make_float4(h[0], h[4], l[0], l[4]);
    float4 c1 = make_float4(h[1], h[5], l[1], l[5]);
    float4 c2 = make_float4(h[2], h[6], l[2], l[6]);
    float4 c3 = make_float4(h[3], h[7], l[3], l[7]);
    size_t o   = (size_t)m * (2 * DM) + g * 16;
    size_t orv = (size_t)(LSEQ - 1 - m) * (2 * DM) + g * 16;
    *reinterpret_cast<float4*>(&g_xiA[0][o])      = c0;
    *reinterpret_cast<float4*>(&g_xiA[0][o + 4])  = c1;
    *reinterpret_cast<float4*>(&g_xiA[0][o + 8])  = c2;
    *reinterpret_cast<float4*>(&g_xiA[0][o + 12]) = c3;
    *reinterpret_cast<float4*>(&g_xiA[1][orv])      = c0;
    *reinterpret_cast<float4*>(&g_xiA[1][orv + 4])  = c1;
    *reinterpret_cast<float4*>(&g_xiA[1][orv + 8])  = c2;
    *reinterpret_cast<float4*>(&g_xiA[1][orv + 12]) = c3;
}

// ---------------- prep: in_w rows n<2048 (tensor half) -> fused tf32 hi/lo ----------------
__global__ void __launch_bounds__(256)
prep_w_kernel(const float* __restrict__ wf, const float* __restrict__ wb)
{
    int gid = blockIdx.x * 256 + threadIdx.x;     // 2 * 2048 * 128 = 524288
    int dir = gid >> 18;
    int r   = gid & 262143;
    int n   = r >> 7;        // 0..2047
    int g   = r & 127;
    const float* src = (dir ? wb : wf) + (size_t)n * DM + g * 8;
    float v[8], h[8], l[8];
#pragma unroll
    for (int i = 0; i < 8; i++) v[i] = src[i];
#pragma unroll
    for (int i = 0; i < 8; i++) {
        h[i] = tf32_round(v[i]);
        l[i] = tf32_round(v[i] - h[i]);
    }
    size_t o = (size_t)n * (2 * DM) + g * 16;
    *reinterpret_cast<float4*>(&g_iwA[dir][o])      = make_float4(h[0], h[4], l[0], l[4]);
    *reinterpret_cast<float4*>(&g_iwA[dir][o + 4])  = make_float4(h[1], h[5], l[1], l[5]);
    *reinterpret_cast<float4*>(&g_iwA[dir][o + 8])  = make_float4(h[2], h[6], l[2], l[6]);
    *reinterpret_cast<float4*>(&g_iwA[dir][o + 12]) = make_float4(h[3], h[7], l[3], l[7]);
}

// ---------------- transpose_all (R9 version): xT, xrevT, inwT, outwT, pwT, dtwT ----------------
__global__ void __launch_bounds__(256)
transpose_all(const float* __restrict__ x,
              const float* __restrict__ inwf, const float* __restrict__ inwb,
              const float* __restrict__ outwf, const float* __restrict__ outwb,
              const float* __restrict__ pw,
              const float* __restrict__ dtwf, const float* __restrict__ dtwb)
{
    __shared__ float t[32][33];
    int b = blockIdx.x;
    const float* S; float* D; int R, Cc; int rev = 0;
    if (b < 2048) {
        S = x; R = 1024; Cc = 1024;
        if (b < 1024) { D = &g_xT[0][0]; }
        else          { D = &g_xrevT[0][0]; rev = 1; b -= 1024; }
    } else if (b < 10240) {
        R = 4096; Cc = 1024;
        if (b < 6144) { S = inwf; D = g_inwT[0]; b -= 2048; }
        else          { S = inwb; D = g_inwT[1]; b -= 6144; }
    } else if (b < 14336) {
        R = 1024; Cc = 2048;
        if (b < 12288) { S = outwf; D = g_outwT[0]; b -= 10240; }
        else           { S = outwb; D = g_outwT[1]; b -= 12288; }
    } else if (b < 16384) {
        S = pw; D = g_pwT; R = 1024; Cc = 2048; b -= 14336;
    } else {
        R = 2048; Cc = 64;
        if (b < 16512) { S = dtwf; D = g_dtwT[0]; b -= 16384; }
        else           { S = dtwb; D = g_dtwT[1]; b -= 16512; }
    }
    int tpr = Cc >> 5;
    int by = b / tpr, bx = b % tpr;
    int r0 = by << 5, c0 = bx << 5;
    int tj  = threadIdx.x & 31;
    int ti4 = (threadIdx.x >> 5) << 2;
#pragma unroll
    for (int i = 0; i < 4; i++)
        t[ti4 + i][tj] = S[(size_t)(r0 + ti4 + i) * Cc + c0 + tj];
    __syncthreads();
    if (!rev) {
#pragma unroll
        for (int i = 0; i < 4; i++)
            D[(size_t)(c0 + ti4 + i) * R + r0 + tj] = t[tj][ti4 + i];
    } else {
#pragma unroll
        for (int i = 0; i < 4; i++)
            D[(size_t)(c0 + ti4 + i) * R + (R - 1 - (r0 + tj))] = t[tj][ti4 + i];
    }
}

// ---------------- hybrid in_proj: tf32-mma CTAs (cols 0..2047) + FFMA2 CTAs (2048..4095) ----------------
// grid dim3(32, 8, 2): engine = x>=16, nt = x&15, dir = z, row0 = y*128.
// shared union buffer: 18432 floats = 73728 B.
__global__ void __launch_bounds__(256, 2)
hybrid_inproj(float* __restrict__ C)
{
    __shared__ __align__(16) float sbuf[18432];

    const int dir  = blockIdx.z;
    const int row0 = blockIdx.y * 128;
    const int nt   = blockIdx.x & 15;
    const int tid  = threadIdx.x;
    const size_t cdo = (size_t)dir * LSEQ * 2 * DI;

    if (blockIdx.x < 16) {
        // ===================== tf32 tensor path, col0 = nt*128 =====================
        constexpr int RS = 36;
        float (*As)[128][RS] = reinterpret_cast<float(*)[128][RS]>(sbuf);          // [2][128][36]
        float (*Bs)[128][RS] = reinterpret_cast<float(*)[128][RS]>(sbuf + 9216);

        const int col0 = nt * 128;
        const float* Ag = g_xiA[dir];
        const float* Bg = g_iwA[dir];

        const int wid  = tid >> 5;
        const int lane = tid & 31;
        const int wm   = wid & 3;
        const int wn   = wid >> 2;
        const int gq   = lane >> 2;
        const int tq   = lane & 3;

        float acc[2][8][4];
#pragma unroll
        for (int i = 0; i < 2; i++)
#pragma unroll
            for (int j = 0; j < 8; j++)
#pragma unroll
                for (int c = 0; c < 4; c++) acc[i][j][c] = 0.f;

        auto issue = [&](int ki, int buf) {
            const int fb = ki * 32;
#pragma unroll
            for (int l = 0; l < 8; l++) {
                int ch = tid + l * 256;
                int q  = ch & 1023;
                int r  = q >> 3;
                int cc = (q & 7) * 4;
                if (ch < 1024) {
                    CP_ASYNC16(smem_u32(&As[buf][r][cc]),
                               Ag + (size_t)(row0 + r) * (2 * DM) + fb + cc);
                } else {
                    CP_ASYNC16(smem_u32(&Bs[buf][r][cc]),
                               Bg + (size_t)(col0 + r) * (2 * DM) + fb + cc);
                }
            }
            CP_COMMIT();
        };

        const int nk = 64;
        issue(0, 0);
        issue(1, 1);

        for (int ki = 0; ki < nk; ki++) {
            if (ki + 1 < nk) { CP_WAIT1(); } else { CP_WAIT0(); }
            __syncthreads();
            const int s = ki & 1;
#pragma unroll
            for (int g = 0; g < 2; g++) {
                const int ko = g * 16 + tq * 4;
                uint32_t ah[2][4], al[2][4];
#pragma unroll
                for (int mi = 0; mi < 2; mi++) {
                    int r = wm * 32 + mi * 16 + gq;
                    float4 a0v = *reinterpret_cast<const float4*>(&As[s][r][ko]);
                    float4 a1v = *reinterpret_cast<const float4*>(&As[s][r + 8][ko]);
                    ah[mi][0] = __float_as_uint(a0v.x); ah[mi][1] = __float_as_uint(a1v.x);
                    ah[mi][2] = __float_as_uint(a0v.y); ah[mi][3] = __float_as_uint(a1v.y);
                    al[mi][0] = __float_as_uint(a0v.z); al[mi][1] = __float_as_uint(a1v.z);
                    al[mi][2] = __float_as_uint(a0v.w); al[mi][3] = __float_as_uint(a1v.w);
                }
#pragma unroll
                for (int ni = 0; ni < 8; ni++) {
                    int nr = wn * 64 + ni * 8 + gq;
                    float4 bv = *reinterpret_cast<const float4*>(&Bs[s][nr][ko]);
                    uint32_t bh0 = __float_as_uint(bv.x), bh1 = __float_as_uint(bv.y);
                    uint32_t bl0 = __float_as_uint(bv.z), bl1 = __float_as_uint(bv.w);
#pragma unroll
                    for (int mi = 0; mi < 2; mi++) {
                        MMA_TF32(acc[mi][ni], ah[mi][0], ah[mi][1], ah[mi][2], ah[mi][3], bh0, bh1);
                        MMA_TF32(acc[mi][ni], ah[mi][0], ah[mi][1], ah[mi][2], ah[mi][3], bl0, bl1);
                        MMA_TF32(acc[mi][ni], al[mi][0], al[mi][1], al[mi][2], al[mi][3], bh0, bh1);
                    }
                }
            }
            __syncthreads();
            if (ki + 2 < nk) issue(ki + 2, s);
        }

#pragma unroll
        for (int mi = 0; mi < 2; mi++) {
            int r0 = row0 + wm * 32 + mi * 16 + gq;
#pragma unroll
            for (int ni = 0; ni < 8; ni++) {
                int c0 = col0 + wn * 64 + ni * 8 + tq * 2;
                *reinterpret_cast<float2*>(&C[cdo + (size_t)r0 * (2 * DI) + c0]) =
                    make_float2(acc[mi][ni][0], acc[mi][ni][1]);
                *reinterpret_cast<float2*>(&C[cdo + (size_t)(r0 + 8) * (2 * DI) + c0]) =
                    make_float2(acc[mi][ni][2], acc[mi][ni][3]);
            }
        }
    } else {
        // ===================== FFMA2 path, col0 = 2048 + nt*128 =====================
        constexpr int BK = 16, ST = 3;
        float (*As)[16][132] = reinterpret_cast<float(*)[16][132]>(sbuf);          // [3][16][132]
        float (*Bs)[16][136] = reinterpret_cast<float(*)[16][136]>(sbuf + 6336);   // [3][16][136]

        const int col0 = 2048 + nt * 128;
        const float* A = dir ? &g_xrevT[0][0] : &g_xT[0][0];  // k-major [1024][LSEQ]
        const float* W = g_inwT[dir];                          // k-major [1024][4096]

        const int tx = tid & 15;
        const int ty = tid >> 4;

        u64t acc2[8][4];
#pragma unroll
        for (int i = 0; i < 8; i++)
#pragma unroll
            for (int j = 0; j < 4; j++) acc2[i][j] = 0ull;

        auto issue = [&](int ki, int buf) {
            const int kb = ki * BK;
#pragma unroll
            for (int l = 0; l < 2; l++) {
                int fi = tid + l * 256;
                int kk = fi >> 5;
                int mc = fi & 31;
                CP_ASYNC16(smem_u32(&As[buf][kk][mc * 4]),
                           A + (size_t)(kb + kk) * LSEQ + row0 + mc * 4);
            }
#pragma unroll
            for (int l = 0; l < 2; l++) {
                int fi = tid + l * 256;
                int kk = fi >> 5, m = fi & 31;
                CP_ASYNC16(smem_u32(&Bs[buf][kk][(m >> 1) * 4 + (m & 1) * 64]),
                           W + (size_t)(kb + kk) * (2 * DI) + col0 + m * 4);
            }
            CP_COMMIT();
        };

        const int nk = DM / BK;   // 64
        issue(0, 0);
        issue(1, 1);

        for (int ki = 0; ki < nk; ki++) {
            if (ki + 1 < nk) { CP_WAIT1(); } else { CP_WAIT0(); }
            __syncthreads();
            if (ki + 2 < nk) issue(ki + 2, (ki + 2) % ST);
            const int cur = ki % ST;
#pragma unroll
            for (int kk = 0; kk < BK; kk++) {
                float a[8];
#pragma unroll
                for (int i = 0; i < 8; i += 4)
                    *reinterpret_cast<float4*>(&a[i]) =
                        *reinterpret_cast<const float4*>(&As[cur][kk][ty * 8 + i]);
                u64t b2[4];
                {
                    ulonglong2 bv0 = *reinterpret_cast<const ulonglong2*>(&Bs[cur][kk][tx * 4]);
                    ulonglong2 bv1 = *reinterpret_cast<const ulonglong2*>(&Bs[cur][kk][64 + tx * 4]);
                    b2[0] = bv0.x; b2[1] = bv0.y;
                    b2[2] = bv1.x; b2[3] = bv1.y;
                }
#pragma unroll
                for (int i = 0; i < 8; i++) {
                    u64t a2 = pack2(a[i], a[i]);
#pragma unroll
                    for (int j = 0; j < 4; j++)
                        FFMA2(acc2[i][j], a2, b2[j], acc2[i][j]);
                }
            }
        }

#pragma unroll
        for (int i = 0; i < 8; i++) {
            int pr = row0 + ty * 8 + i;
#pragma unroll
            for (int j = 0; j < 4; j++) {
                float v0, v1;
                unpack2(acc2[i][j], v0, v1);
                int c0 = col0 + tx * 8 + j * 2;
                C[cdo + (size_t)pr * (2 * DI) + c0]     = v0;
                C[cdo + (size_t)pr * (2 * DI) + c0 + 1] = v1;
            }
        }
    }
}

// ---------------- transpose_cat ----------------
__global__ void __launch_bounds__(256)
transpose_cat()
{
    __shared__ float t[32][33];
    int b  = blockIdx.x;
    int by = b >> 6, bx = b & 63;
    int r0 = by << 5, c0 = bx << 5;
    int tj  = threadIdx.x & 31;
    int ti4 = (threadIdx.x >> 5) << 2;
#pragma unroll
    for (int i = 0; i < 4; i++)
        t[ti4 + i][tj] = g_cat[r0 + ti4 + i][c0 + tj];
    __syncthreads();
#pragma unroll
    for (int i = 0; i < 4; i++)
        g_catT[c0 + ti4 + i][r0 + tj] = t[tj][ti4 + i];
}

// ---------------- NT SGEMM, f32x2, cp.async 3-stage, split-K capable ----------------
template<int BM, int BK, int MINB>
__global__ void __launch_bounds__(256, MINB)
sgemm_ca(const float* __restrict__ Af, const float* __restrict__ Ab, int ldm,
         const float* __restrict__ Wf, const float* __restrict__ Wb, int ldn,
         float* __restrict__ C, size_t cdoff, size_t sdoff, int nsplit,
         int ldc, int crevd,
         int M, int K, int epi,
         const float* __restrict__ biasf, const float* __restrict__ biasb,
         const float* __restrict__ resid, int ldr)
{
    constexpr int BN = 128;
    constexpr int TM = BM / 16;
    constexpr int NAc = (BM * BK) / 1024;
    constexpr int NBc = BK / 8;
    constexpr int ST = 3;
    __shared__ __align__(16) float As[ST][BK][BM + 4];
    __shared__ __align__(16) float Bs[ST][BK][BN + 8];

    const int s   = blockIdx.z % nsplit;
    const int dir = blockIdx.z / nsplit;
    const float* A    = (dir ? Ab : Af) + (size_t)s * K * ldm;
    const float* W    = (dir ? Wb : Wf) + (size_t)s * K * ldn;
    const float* bias = dir ? biasb : biasf;
    const int crev = crevd & -dir;
    const size_t cdo = (size_t)dir * cdoff + (size_t)s * sdoff;

    const int tid  = threadIdx.x;
    const int row0 = blockIdx.y * BM;
    const int col0 = blockIdx.x * BN;
    const int tx   = tid & 15;
    const int ty   = tid >> 4;

    u64t acc2[TM][4];
#pragma unroll
    for (int i = 0; i < TM; i++)
#pragma unroll
        for (int j = 0; j < 4; j++) acc2[i][j] = 0ull;

    auto issue = [&](int ki, int buf) {
        const int kb = ki * BK;
#pragma unroll
        for (int l = 0; l < NAc; l++) {
            int fi = tid + l * 256;
            int kk = fi / (BM / 4);
            int mc = fi % (BM / 4);
            uint32_t dst = smem_u32(&As[buf][kk][mc * 4]);
            const float* src = A + (size_t)(kb + kk) * ldm + row0 + mc * 4;
            CP_ASYNC16(dst, src);
        }
#pragma unroll
        for (int l = 0; l < NBc; l++) {
            int fi = tid + l * 256;
            int kk = fi >> 5, m = fi & 31;
            uint32_t dst = smem_u32(&Bs[buf][kk][(m >> 1) * 4 + (m & 1) * 64]);
            const float* src = W + (size_t)(kb + kk) * ldn + col0 + m * 4;
            CP_ASYNC16(dst, src);
        }
        CP_COMMIT();
    };

    const int nk = K / BK;
    issue(0, 0);
    if (nk > 1) issue(1, 1);

    for (int ki = 0; ki < nk; ki++) {
        if (ki + 1 < nk) { CP_WAIT1(); } else { CP_WAIT0(); }
        __syncthreads();
        if (ki + 2 < nk) issue(ki + 2, (ki + 2) % ST);
        const int cur = ki % ST;
#pragma unroll
        for (int kk = 0; kk < BK; kk++) {
            float a[TM];
#pragma unroll
            for (int i = 0; i < TM; i += 4)
                *reinterpret_cast<float4*>(&a[i]) =
                    *reinterpret_cast<const float4*>(&As[cur][kk][ty * TM + i]);
            u64t b2[4];
            {
                ulonglong2 bv0 = *reinterpret_cast<const ulonglong2*>(&Bs[cur][kk][tx * 4]);
                ulonglong2 bv1 = *reinterpret_cast<const ulonglong2*>(&Bs[cur][kk][64 + tx * 4]);
                b2[0] = bv0.x; b2[1] = bv0.y;
                b2[2] = bv1.x; b2[3] = bv1.y;
            }
#pragma unroll
            for (int i = 0; i < TM; i++) {
                u64t a2 = pack2(a[i], a[i]);
#pragma unroll
                for (int j = 0; j < 4; j++)
                    FFMA2(acc2[i][j], a2, b2[j], acc2[i][j]);
            }
        }
    }

#pragma unroll
    for (int i = 0; i < TM; i++) {
        int lr = row0 + ty * TM + i;
        int pr = crev ? (M - 1 - lr) : lr;
#pragma unroll
        for (int j = 0; j < 4; j++) {
            float v0, v1;
            unpack2(acc2[i][j], v0, v1);
            int c0 = col0 + tx * 8 + j * 2;
            if (epi == 1) {
                v0 = softplus_f(v0 + bias[c0]);
                v1 = softplus_f(v1 + bias[c0 + 1]);
            } else if (epi == 2) {
                v0 += resid[(size_t)pr * ldr + c0];
                v1 += resid[(size_t)pr * ldr + c0 + 1];
            } else if (epi == 3) {
                v0 += bias[c0];
                v1 += bias[c0 + 1];
            }
            C[cdo + (size_t)pr * ldc + c0]     = v0;
            C[cdo + (size_t)pr * ldc + c0 + 1] = v1;
        }
    }
}

// ---------------- out_reduce ----------------
__global__ void __launch_bounds__(256)
out_reduce(const float* __restrict__ x)
{
    int idx = blockIdx.x * blockDim.x + threadIdx.x;
    int c   = idx & (DM - 1);
    int t   = (idx >> 10) & (LSEQ - 1);
    int dir = idx >> 20;
    int pr  = dir ? (LSEQ - 1 - t) : t;
    float v = g_opart[dir][0][t][c] + g_opart[dir][1][t][c] + x[(size_t)pr * DM + c];
    g_cat[pr][dir * DM + c] = v;
}

// ---------------- conv + silu ----------------
__global__ void conv_silu_kernel(const float* __restrict__ cwf, const float* __restrict__ cbf,
                                 const float* __restrict__ cwb, const float* __restrict__ cbb)
{
    int idx = blockIdx.x * blockDim.x + threadIdx.x;
    int d   = idx & (DI - 1);
    int t   = (idx >> 11) & (LSEQ - 1);
    int dir = idx >> 21;
    const float* cw = dir ? cwb : cwf;
    const float* cb = dir ? cbb : cbf;
    float w0 = cw[d * 4 + 0], w1 = cw[d * 4 + 1], w2 = cw[d * 4 + 2], w3 = cw[d * 4 + 3];
    const float* xi = &g_xz[dir][0][d];
    float acc = cb[d];
    if (t >= 3) acc += w0 * xi[(t - 3) * (2 * DI)];
    if (t >= 2) acc += w1 * xi[(t - 2) * (2 * DI)];
    if (t >= 1) acc += w2 * xi[(t - 1) * (2 * DI)];
    acc += w3 * xi[t * (2 * DI)];
    g_u[dir][t][d] = acc * sigmoid_f(acc);
}

// ---------------- x-proj: 16-way split-K ----------------
__global__ void __launch_bounds__(256)
xproj_partial_kernel(const float* __restrict__ wf, const float* __restrict__ wb)
{
    const int chunk = blockIdx.x;
    const int mb    = blockIdx.y;
    const int dir   = blockIdx.z;
    const float* W  = dir ? wb : wf;
    const int row0  = mb * 32;
    const int kbase = chunk * 128;
    const int tid   = threadIdx.x;

    __shared__ __align__(16) float Us[32][36];
    __shared__ __align__(16) float Ws[32][100];

    const int tx = tid & 15;
    const int ty = tid >> 4;
    float acc[2][6];
#pragma unroll
    for (int i = 0; i < 2; i++)
#pragma unroll
        for (int j = 0; j < 6; j++) acc[i][j] = 0.f;

#pragma unroll
    for (int k0 = 0; k0 < 128; k0 += 32) {
        {
            int r  = tid >> 3;
            int kk = (tid & 7) << 2;
            float4 v = *reinterpret_cast<const float4*>(&g_u[dir][row0 + r][kbase + k0 + kk]);
            Us[kk + 0][r] = v.x; Us[kk + 1][r] = v.y;
            Us[kk + 2][r] = v.z; Us[kk + 3][r] = v.w;
        }
#pragma unroll
        for (int l = 0; l < 3; l++) {
            int fi = tid + l * 256;
            int n  = fi >> 3;
            int kk = (fi & 7) << 2;
            float4 v = *reinterpret_cast<const float4*>(&W[(size_t)n * DI + kbase + k0 + kk]);
            Ws[kk + 0][n] = v.x; Ws[kk + 1][n] = v.y;
            Ws[kk + 2][n] = v.z; Ws[kk + 3][n] = v.w;
        }
        __syncthreads();
#pragma unroll
        for (int kk = 0; kk < 32; kk++) {
            float a0 = Us[kk][ty * 2 + 0];
            float a1 = Us[kk][ty * 2 + 1];
#pragma unroll
            for (int j = 0; j < 6; j++) {
                float bv = Ws[kk][tx * 6 + j];
                acc[0][j] = fmaf(a0, bv, acc[0][j]);
                acc[1][j] = fmaf(a1, bv, acc[1][j]);
            }
        }
        __syncthreads();
    }
#pragma unroll
    for (int i = 0; i < 2; i++)
#pragma unroll
        for (int j = 0; j < 6; j++)
            g_xdbl_part[dir][chunk][row0 + ty * 2 + i][tx * 6 + j] = acc[i][j];
}

__global__ void xdbl_reduce_kernel()
{
    int idx = blockIdx.x * blockDim.x + threadIdx.x;
    int c   = idx % 96;
    int t   = (idx / 96) & (LSEQ - 1);
    int dir = idx / (96 * LSEQ);
    float s = 0.f;
#pragma unroll
    for (int ch = 0; ch < 16; ch++) s += g_xdbl_part[dir][ch][t][c];
    g_xdbl[dir][t][c] = s;
    if (c < DTR) g_xdT[dir][c][t] = s;
}

// ---------------- selective scan ----------------
__global__ void __launch_bounds__(128)
scan_kernel(const float* __restrict__ Alf, const float* __restrict__ Dpf,
            const float* __restrict__ Alb, const float* __restrict__ Dpb)
{
    int gid = blockIdx.x * 128 + threadIdx.x;
    int q   = gid & 3;
    int grp = gid >> 2;
    int dir = grp >> 11;
    int d   = grp & (DI - 1);

    const float* Alog = dir ? Alb : Alf;
    float dp = (dir ? Dpb : Dpf)[d];
    float Aa[4];
#pragma unroll
    for (int j = 0; j < 4; j++) Aa[j] = -expf(Alog[d * DS + q * 4 + j]);

    const float* dep = &g_delta[dir][0][d];
    const float* up  = &g_u[dir][0][d];
    const float* zp  = &g_xz[dir][0][DI + d];
    const float* bcp = &g_xdbl[dir][0][DTR + q * 4];
    float* ypT = &g_y2T[dir][d][0];

    float h0 = 0.f, h1 = 0.f, h2 = 0.f, h3 = 0.f;

    float dA[4], uA[4], zA[4]; float4 BA[4], CA[4];
    float dB[4], uB[4], zB[4]; float4 BB[4], CB[4];

#define LOADCH(t0, dv, uv, zv, Bv, Cv) do {                                   \
    _Pragma("unroll")                                                         \
    for (int i = 0; i < 4; i++) {                                             \
        dv[i] = dep[((t0) + i) * DI];                                         \
        uv[i] = up [((t0) + i) * DI];                                         \
        zv[i] = zp [((t0) + i) * (2 * DI)];                                   \
        Bv[i] = *reinterpret_cast<const float4*>(bcp + ((t0) + i) * 96);      \
        Cv[i] = *reinterpret_cast<const float4*>(bcp + ((t0) + i) * 96 + DS); \
    } } while (0)

#define COMPCH(t0, dv, uv, zv, Bv, Cv) do {                                   \
    float yout[4];                                                            \
    _Pragma("unroll")                                                         \
    for (int i = 0; i < 4; i++) {                                             \
        float dc = dv[i], uc = uv[i], zc = zv[i];                             \
        float4 Bc = Bv[i], Cc = Cv[i];                                        \
        float db = dc * uc;                                                   \
        float e0 = __expf(dc * Aa[0]);                                        \
        float e1 = __expf(dc * Aa[1]);                                        \
        float e2 = __expf(dc * Aa[2]);                                        \
        float e3 = __expf(dc * Aa[3]);                                        \
        h0 = fmaf(e0, h0, db * Bc.x);                                         \
        h1 = fmaf(e1, h1, db * Bc.y);                                         \
        h2 = fmaf(e2, h2, db * Bc.z);                                         \
        h3 = fmaf(e3, h3, db * Bc.w);                                         \
        float p = h0 * Cc.x + h1 * Cc.y + h2 * Cc.z + h3 * Cc.w;              \
        p += __shfl_xor_sync(0xffffffffu, p, 1);                              \
        p += __shfl_xor_sync(0xffffffffu, p, 2);                              \
        if (q == 0) yout[i] = (p + uc * dp) * zc * sigmoid_f(zc);             \
    }                                                                         \
    if (q == 0) {                                                             \
        float4 v; v.x = yout[0]; v.y = yout[1]; v.z = yout[2]; v.w = yout[3]; \
        *reinterpret_cast<float4*>(ypT + (t0)) = v;                           \
    } } while (0)

    LOADCH(0, dA, uA, zA, BA, CA);
    for (int c = 0; c < LSEQ / 4; c += 2) {
        if (c + 1 < LSEQ / 4) LOADCH((c + 1) * 4, dB, uB, zB, BB, CB);
        COMPCH(c * 4, dA, uA, zA, BA, CA);
        if (c + 2 < LSEQ / 4) LOADCH((c + 2) * 4, dA, uA, zA, BA, CA);
        COMPCH((c + 1) * 4, dB, uB, zB, BB, CB);
    }
#undef LOADCH
#undef COMPCH
}

// ---------------- layernorm fused with final-proj split-K reduce ----------------
__global__ void __launch_bounds__(256)
layernorm_kernel(const float* __restrict__ pbias,
                 const float* __restrict__ lw, const float* __restrict__ lb,
                 float* __restrict__ out)
{
    int row = blockIdx.x;
    float vr[4];
    float s = 0.f, s2 = 0.f;
#pragma unroll
    for (int l = 0; l < 4; l++) {
        int i = threadIdx.x + l * 256;
        float v = pbias[i]
                + g_fpart[0][row][i] + g_fpart[1][row][i]
                + g_fpart[2][row][i] + g_fpart[3][row][i];
        vr[l] = v;
        s += v; s2 += v * v;
    }
#pragma unroll
    for (int o = 16; o > 0; o >>= 1) {
        s  += __shfl_xor_sync(0xffffffffu, s,  o);
        s2 += __shfl_xor_sync(0xffffffffu, s2, o);
    }
    __shared__ float sm1[8], sm2[8];
    __shared__ float mu_s, rs_s;
    int w = threadIdx.x >> 5;
    if ((threadIdx.x & 31) == 0) { sm1[w] = s; sm2[w] = s2; }
    __syncthreads();
    if (threadIdx.x == 0) {
        float S = 0.f, S2 = 0.f;
#pragma unroll
        for (int i = 0; i < 8; i++) { S += sm1[i]; S2 += sm2[i]; }
        float mu  = S * (1.f / DM);
        float var = S2 * (1.f / DM) - mu * mu;
        mu_s = mu;
        rs_s = rsqrtf(var + 1e-5f);
    }
    __syncthreads();
    float mu = mu_s, rs = rs_s;
#pragma unroll
    for (int l = 0; l < 4; l++) {
        int i = threadIdx.x + l * 256;
        out[(size_t)row * DM + i] = (vr[l] - mu) * rs * lw[i] + lb[i];
    }
}

// ---------------- launch ----------------
extern "C" void kernel_launch(void* const* d_in, const int* in_sizes, int n_in,
                              void* d_out, int out_size)
{
    const float* x         = (const float*)d_in[0];
    const float* fw_in_w   = (const float*)d_in[1];
    const float* fw_conv_w = (const float*)d_in[2];
    const float* fw_conv_b = (const float*)d_in[3];
    const float* fw_xproj  = (const float*)d_in[4];
    const float* fw_dt_w   = (const float*)d_in[5];
    const float* fw_dt_b   = (const float*)d_in[6];
    const float* fw_Alog   = (const float*)d_in[7];
    const float* fw_Dp     = (const float*)d_in[8];
    const float* fw_out_w  = (const float*)d_in[9];
    const float* bw_in_w   = (const float*)d_in[10];
    const float* bw_conv_w = (const float*)d_in[11];
    const float* bw_conv_b = (const float*)d_in[12];
    const float* bw_xproj  = (const float*)d_in[13];
    const float* bw_dt_w   = (const float*)d_in[14];
    const float* bw_dt_b   = (const float*)d_in[15];
    const float* bw_Alog   = (const float*)d_in[16];
    const float* bw_Dp     = (const float*)d_in[17];
    const float* bw_out_w  = (const float*)d_in[18];
    const float* proj_w    = (const float*)d_in[19];
    const float* proj_b    = (const float*)d_in[20];
    const float* ln_w      = (const float*)d_in[21];
    const float* ln_b      = (const float*)d_in[22];
    float* out = (float*)d_out;

    float *xz, *del, *dtwT, *xdT, *y2T, *outwT, *pwT, *opart, *fpart, *catT;
    cudaGetSymbolAddress((void**)&xz,    g_xz);
    cudaGetSymbolAddress((void**)&del,   g_delta);
    cudaGetSymbolAddress((void**)&outwT, g_outwT);
    cudaGetSymbolAddress((void**)&pwT,   g_pwT);
    cudaGetSymbolAddress((void**)&dtwT,  g_dtwT);
    cudaGetSymbolAddress((void**)&xdT,   g_xdT);
    cudaGetSymbolAddress((void**)&y2T,   g_y2T);
    cudaGetSymbolAddress((void**)&catT,  g_catT);
    cudaGetSymbolAddress((void**)&opart, g_opart);
    cudaGetSymbolAddress((void**)&fpart, g_fpart);

    const size_t OUTW = (size_t)DI * DM;
    const size_t DTW = (size_t)DTR * DI;
    const size_t XDT = (size_t)DTR * LSEQ;
    const size_t Y2T = (size_t)DI * LSEQ;
    const size_t PLANE = (size_t)LSEQ * DM;

    // 0-2) transposes + tf32 prep (profiler anchors; in_proj at idx 3)
    transpose_all<<<16640, 256>>>(x, fw_in_w, bw_in_w, fw_out_w, bw_out_w,
                                  proj_w, fw_dt_w, bw_dt_w);
    prep_x_kernel<<<512, 256>>>(x);
    prep_w_kernel<<<2048, 256>>>(fw_in_w, bw_in_w);

    // 3) hybrid in_proj: tensor half (cols<2048) + FFMA2 half (cols>=2048)
    hybrid_inproj<<<dim3(32, 8, 2), 256>>>(xz);

    // 4) conv + silu -> u
    conv_silu_kernel<<<(2 * LSEQ * DI) / 256, 256>>>(fw_conv_w, fw_conv_b, bw_conv_w, bw_conv_b);

    // 5) x-proj (16-way split-K) -> x_dbl (+ k-major dt cols)
    dim3 gx(16, 32, 2);
    xproj_partial_kernel<<<gx, 256>>>(fw_xproj, bw_xproj);
    xdbl_reduce_kernel<<<(2 * LSEQ * 96) / 256, 256>>>();

    // 6) delta = softplus(dt @ dt_w^T + dt_b)
    sgemm_ca<128,32,2><<<dim3(16, 8, 2), 256>>>(
        xdT, xdT + XDT, LSEQ, dtwT, dtwT + DTW, DI,
        del, (size_t)LSEQ * DI, 0, 1, DI, 0,
        LSEQ, DTR, 1, fw_dt_b, bw_dt_b, nullptr, 0);

    // 7) selective scan -> y2^T
    scan_kernel<<<128, 128>>>(fw_Alog, fw_Dp, bw_Alog, bw_Dp);

    // 8) out_proj split-K2 -> opart
    sgemm_ca<128,32,2><<<dim3(8, 8, 4), 256>>>(
        y2T, y2T + Y2T, LSEQ, outwT, outwT + OUTW, DM,
        opart, 2 * PLANE, PLANE, 2, DM, 0,
        LSEQ, DI / 2, 0, nullptr, nullptr, nullptr, 0);

    // 9) reduce partials + residual -> cat
    out_reduce<<<(2 * LSEQ * DM) / 256, 256>>>(x);

    // 10) cat -> catT
    transpose_cat<<<2048, 256>>>();

    // 11) final proj split-K4 -> fpart
    sgemm_ca<128,32,2><<<dim3(8, 8, 4), 256>>>(
        catT, catT, LSEQ, pwT, pwT, DM,
        fpart, 0, PLANE, 4, DM, 0,
        LSEQ, 2 * DM / 4, 0, nullptr, nullptr, nullptr, 0);

    // 12) layernorm (fused split-K reduce + bias) -> out
    layernorm_kernel<<<LSEQ, 256>>>(proj_b, ln_w, ln_b, out);
}

// round 17
// speedup vs baseline: 1.2684x; 1.2684x over previous
#include <cuda_runtime.h>
#include <cuda_bf16.h>
#include <math.h>
#include <stdint.h>

#define LSEQ 1024
#define DM   1024
#define DI   2048
#define DS   16
#define DTR  64

// ---------------- scratch ----------------
__device__ __align__(16) float g_xz[2][LSEQ][2*DI];
__device__ __align__(16) float g_u [2][LSEQ][DI];
__device__ __align__(16) float g_xdbl_part[2][16][LSEQ][96];
__device__ __align__(16) float g_xdbl[2][LSEQ][96];
__device__ __align__(16) float g_delta[2][LSEQ][DI];
__device__ __align__(16) float g_cat[LSEQ][2*DM];
__device__ __align__(16) float g_opart[2][2][LSEQ][DM];
__device__ __align__(16) float g_fpart[4][LSEQ][DM];

// fused bf16 hi/lo operands for in_proj (chunk layout, see prep kernels)
// row = DM floats (K values * (hi+lo) * 2B = 4K bytes)
__device__ __align__(16) float g_xiB[2][LSEQ * DM];       // dir0 natural, dir1 row-reversed
__device__ __align__(16) float g_iwB[2][2 * DI * DM];     // in_w rows (n-major)

// k-major fp32 operands for cp.async FFMA2 GEMMs
__device__ __align__(16) float g_outwT[2][DI * DM];
__device__ __align__(16) float g_pwT  [2 * DM * DM];
__device__ __align__(16) float g_dtwT [2][DTR * DI];
__device__ __align__(16) float g_xdT  [2][DTR][LSEQ];
__device__ __align__(16) float g_y2T  [2][DI][LSEQ];
__device__ __align__(16) float g_catT [2 * DM][LSEQ];

__device__ __forceinline__ float sigmoid_f(float x) {
    return __fdividef(1.f, 1.f + __expf(-x));
}
__device__ __forceinline__ float softplus_f(float x) {
    return (x > 20.f) ? x : log1pf(__expf(x));
}

typedef unsigned long long u64t;
__device__ __forceinline__ u64t pack2(float lo, float hi) {
    u64t r;
    asm("mov.b64 %0, {%1, %2};" : "=l"(r) : "r"(__float_as_uint(lo)), "r"(__float_as_uint(hi)));
    return r;
}
__device__ __forceinline__ void unpack2(u64t v, float& lo, float& hi) {
    uint32_t a, b;
    asm("mov.b64 {%0, %1}, %2;" : "=r"(a), "=r"(b) : "l"(v));
    lo = __uint_as_float(a);
    hi = __uint_as_float(b);
}
#define FFMA2(d, a, b, c) \
    asm("fma.rn.f32x2 %0, %1, %2, %3;" : "=l"(d) : "l"(a), "l"(b), "l"(c))

// bf16 m16n8k16 mma: D(16x8,f32) += A(16x16,bf16) * B(16x8,bf16)
#define MMA_BF16(c, a0, a1, a2, a3, b0, b1) \
    asm volatile("mma.sync.aligned.m16n8k16.row.col.f32.bf16.bf16.f32 " \
        "{%0,%1,%2,%3}, {%4,%5,%6,%7}, {%8,%9}, {%0,%1,%2,%3};" \
        : "+f"((c)[0]), "+f"((c)[1]), "+f"((c)[2]), "+f"((c)[3]) \
        : "r"(a0), "r"(a1), "r"(a2), "r"(a3), "r"(b0), "r"(b1))

__device__ __forceinline__ uint32_t smem_u32(const void* p) {
    return (uint32_t)__cvta_generic_to_shared(p);
}
#define CP_ASYNC16(dst, src) \
    asm volatile("cp.async.cg.shared.global [%0], [%1], 16;" :: "r"(dst), "l"(src) : "memory")
#define CP_COMMIT() asm volatile("cp.async.commit_group;" ::: "memory")
#define CP_WAIT1()  asm volatile("cp.async.wait_group 1;" ::: "memory")
#define CP_WAIT0()  asm volatile("cp.async.wait_group 0;" ::: "memory")

// ---------------- bf16 hi/lo split + chunk pack ----------------
// per 16-k group, chunk tq (16B): {hi(2tq,2tq+1), lo(2tq,2tq+1), hi(2tq+8,+9), lo(2tq+8,+9)}
__device__ __forceinline__ uint32_t bf2pack(float e, float o) {
    __nv_bfloat162 p;
    p.x = __float2bfloat16(e);
    p.y = __float2bfloat16(o);
    return *reinterpret_cast<uint32_t*>(&p);
}
__device__ __forceinline__ void split16(const float* v, uint32_t* w) {
    float h[16], l[16];
#pragma unroll
    for (int i = 0; i < 16; i++) {
        __nv_bfloat16 hb = __float2bfloat16(v[i]);
        h[i] = __bfloat162float(hb);
        l[i] = v[i] - h[i];
    }
#pragma unroll
    for (int tq = 0; tq < 4; tq++) {
        w[tq * 4 + 0] = bf2pack(h[2 * tq],     h[2 * tq + 1]);
        w[tq * 4 + 1] = bf2pack(l[2 * tq],     l[2 * tq + 1]);
        w[tq * 4 + 2] = bf2pack(h[2 * tq + 8], h[2 * tq + 9]);
        w[tq * 4 + 3] = bf2pack(l[2 * tq + 8], l[2 * tq + 9]);
    }
}

// ---------------- prep: x -> fused bf16 hi/lo (fw + reversed) ----------------
__global__ void __launch_bounds__(256)
prep_x_kernel(const float* __restrict__ x)
{
    int gid = blockIdx.x * 256 + threadIdx.x;   // LSEQ * 64 = 65536
    int m = gid >> 6;
    int g = gid & 63;
    float v[16];
    const float* src = x + (size_t)m * DM + g * 16;
#pragma unroll
    for (int i = 0; i < 16; i++) v[i] = src[i];
    uint32_t w[16];
    split16(v, w);
    size_t o   = (size_t)m * DM + g * 16;
    size_t orv = (size_t)(LSEQ - 1 - m) * DM + g * 16;
#pragma unroll
    for (int c = 0; c < 4; c++) {
        uint4 u = make_uint4(w[c * 4], w[c * 4 + 1], w[c * 4 + 2], w[c * 4 + 3]);
        *reinterpret_cast<uint4*>(&g_xiB[0][o + c * 4])   = u;
        *reinterpret_cast<uint4*>(&g_xiB[1][orv + c * 4]) = u;
    }
}

// ---------------- prep: in_w (both dirs) -> fused bf16 hi/lo ----------------
__global__ void __launch_bounds__(256)
prep_w_kernel(const float* __restrict__ wf, const float* __restrict__ wb)
{
    int gid = blockIdx.x * 256 + threadIdx.x;   // 2 * 4096 * 64 = 524288
    int dir = gid >> 18;
    int r   = gid & 262143;
    int n   = r >> 6;
    int g   = r & 63;
    float v[16];
    const float* src = (dir ? wb : wf) + (size_t)n * DM + g * 16;
#pragma unroll
    for (int i = 0; i < 16; i++) v[i] = src[i];
    uint32_t w[16];
    split16(v, w);
    size_t o = (size_t)n * DM + g * 16;
#pragma unroll
    for (int c = 0; c < 4; c++)
        *reinterpret_cast<uint4*>(&g_iwB[dir][o + c * 4]) =
            make_uint4(w[c * 4], w[c * 4 + 1], w[c * 4 + 2], w[c * 4 + 3]);
}

// ---------------- in_proj via bf16 mma.sync m16n8k16, 3-term compensation ----------------
// CTA 128x128, BK=32 (2 k-groups/stage), ST=2, RS=40 (160B rows, 16B-aligned).
// 8 warps: (wm=wid&3)*32 rows x (wn=wid>>2)*64 cols.
__global__ void __launch_bounds__(256, 2)
mma_inproj(float* __restrict__ C)
{
    constexpr int BM = 128, BN = 128, BK = 32, ST = 2, RS = 40;
    __shared__ __align__(16) float As[ST][BM][RS];
    __shared__ __align__(16) float Bs[ST][BN][RS];

    const int dir  = blockIdx.z;
    const int row0 = blockIdx.y * BM;
    const int col0 = blockIdx.x * BN;
    const float* Ag = g_xiB[dir];
    const float* Bg = g_iwB[dir];
    const size_t cdo = (size_t)dir * LSEQ * 2 * DI;

    const int tid  = threadIdx.x;
    const int wid  = tid >> 5;
    const int lane = tid & 31;
    const int wm   = wid & 3;
    const int wn   = wid >> 2;
    const int gq   = lane >> 2;
    const int tq   = lane & 3;

    float acc[2][8][4];
#pragma unroll
    for (int i = 0; i < 2; i++)
#pragma unroll
        for (int j = 0; j < 8; j++)
#pragma unroll
            for (int c = 0; c < 4; c++) acc[i][j][c] = 0.f;

    // per stage: 128 rows x 32 floats (8 chunks of 16B) per matrix = 1024 chunks each
    auto issue = [&](int ki, int buf) {
        const int fb = ki * BK;   // float col base (1 float per k: (hi+lo)*2B)
#pragma unroll
        for (int l = 0; l < 8; l++) {
            int ch = tid + l * 256;            // 0..2047
            int q  = ch & 1023;
            int r  = q >> 3;
            int cc = (q & 7) * 4;
            if (ch < 1024) {
                CP_ASYNC16(smem_u32(&As[buf][r][cc]),
                           Ag + (size_t)(row0 + r) * DM + fb + cc);
            } else {
                CP_ASYNC16(smem_u32(&Bs[buf][r][cc]),
                           Bg + (size_t)(col0 + r) * DM + fb + cc);
            }
        }
        CP_COMMIT();
    };

    const int nk = DM / BK;   // 32
    issue(0, 0);
    issue(1, 1);

    for (int ki = 0; ki < nk; ki++) {
        if (ki + 1 < nk) { CP_WAIT1(); } else { CP_WAIT0(); }
        __syncthreads();
        const int s = ki & 1;
#pragma unroll
        for (int g = 0; g < 2; g++) {
            const int ko = g * 16 + tq * 4;
            uint32_t a0h[2], a1h[2], a2h[2], a3h[2];
            uint32_t a0l[2], a1l[2], a2l[2], a3l[2];
#pragma unroll
            for (int mi = 0; mi < 2; mi++) {
                int r = wm * 32 + mi * 16 + gq;
                float4 av0 = *reinterpret_cast<const float4*>(&As[s][r][ko]);
                float4 av1 = *reinterpret_cast<const float4*>(&As[s][r + 8][ko]);
                a0h[mi] = __float_as_uint(av0.x); a0l[mi] = __float_as_uint(av0.y);
                a2h[mi] = __float_as_uint(av0.z); a2l[mi] = __float_as_uint(av0.w);
                a1h[mi] = __float_as_uint(av1.x); a1l[mi] = __float_as_uint(av1.y);
                a3h[mi] = __float_as_uint(av1.z); a3l[mi] = __float_as_uint(av1.w);
            }
#pragma unroll
            for (int ni = 0; ni < 8; ni++) {
                int nr = wn * 64 + ni * 8 + gq;
                float4 bv = *reinterpret_cast<const float4*>(&Bs[s][nr][ko]);
                uint32_t b0h = __float_as_uint(bv.x), b0l = __float_as_uint(bv.y);
                uint32_t b1h = __float_as_uint(bv.z), b1l = __float_as_uint(bv.w);
#pragma unroll
                for (int mi = 0; mi < 2; mi++) {
                    MMA_BF16(acc[mi][ni], a0h[mi], a1h[mi], a2h[mi], a3h[mi], b0h, b1h);
                    MMA_BF16(acc[mi][ni], a0h[mi], a1h[mi], a2h[mi], a3h[mi], b0l, b1l);
                    MMA_BF16(acc[mi][ni], a0l[mi], a1l[mi], a2l[mi], a3l[mi], b0h, b1h);
                }
            }
        }
        __syncthreads();                       // buffer s fully consumed
        if (ki + 2 < nk) issue(ki + 2, s);     // refill freed buffer
    }

#pragma unroll
    for (int mi = 0; mi < 2; mi++) {
        int r0 = row0 + wm * 32 + mi * 16 + gq;
#pragma unroll
        for (int ni = 0; ni < 8; ni++) {
            int c0 = col0 + wn * 64 + ni * 8 + tq * 2;
            *reinterpret_cast<float2*>(&C[cdo + (size_t)r0 * (2 * DI) + c0]) =
                make_float2(acc[mi][ni][0], acc[mi][ni][1]);
            *reinterpret_cast<float2*>(&C[cdo + (size_t)(r0 + 8) * (2 * DI) + c0]) =
                make_float2(acc[mi][ni][2], acc[mi][ni][3]);
        }
    }
}

// ---------------- transpose_all: k-major fp32 operands (outw, pw, dtw) ----------------
__global__ void __launch_bounds__(256)
transpose_all(const float* __restrict__ outwf, const float* __restrict__ outwb,
              const float* __restrict__ pw,
              const float* __restrict__ dtwf, const float* __restrict__ dtwb)
{
    __shared__ float t[32][33];
    int b = blockIdx.x;
    const float* S; float* D; int R, Cc;
    if (b < 4096) {
        R = 1024; Cc = 2048;
        if (b < 2048) { S = outwf; D = g_outwT[0]; }
        else          { S = outwb; D = g_outwT[1]; b -= 2048; }
    } else if (b < 6144) {
        S = pw; D = g_pwT; R = 1024; Cc = 2048; b -= 4096;
    } else {
        R = 2048; Cc = 64;
        if (b < 6272) { S = dtwf; D = g_dtwT[0]; b -= 6144; }
        else          { S = dtwb; D = g_dtwT[1]; b -= 6272; }
    }
    int tpr = Cc >> 5;
    int by = b / tpr, bx = b % tpr;
    int r0 = by << 5, c0 = bx << 5;
    int tj  = threadIdx.x & 31;
    int ti4 = (threadIdx.x >> 5) << 2;
#pragma unroll
    for (int i = 0; i < 4; i++)
        t[ti4 + i][tj] = S[(size_t)(r0 + ti4 + i) * Cc + c0 + tj];
    __syncthreads();
#pragma unroll
    for (int i = 0; i < 4; i++)
        D[(size_t)(c0 + ti4 + i) * R + r0 + tj] = t[tj][ti4 + i];
}

// ---------------- transpose_cat ----------------
__global__ void __launch_bounds__(256)
transpose_cat()
{
    __shared__ float t[32][33];
    int b  = blockIdx.x;
    int by = b >> 6, bx = b & 63;
    int r0 = by << 5, c0 = bx << 5;
    int tj  = threadIdx.x & 31;
    int ti4 = (threadIdx.x >> 5) << 2;
#pragma unroll
    for (int i = 0; i < 4; i++)
        t[ti4 + i][tj] = g_cat[r0 + ti4 + i][c0 + tj];
    __syncthreads();
#pragma unroll
    for (int i = 0; i < 4; i++)
        g_catT[c0 + ti4 + i][r0 + tj] = t[tj][ti4 + i];
}

// ---------------- NT SGEMM, f32x2, cp.async 3-stage, split-K capable ----------------
template<int BM, int BK, int MINB>
__global__ void __launch_bounds__(256, MINB)
sgemm_ca(const float* __restrict__ Af, const float* __restrict__ Ab, int ldm,
         const float* __restrict__ Wf, const float* __restrict__ Wb, int ldn,
         float* __restrict__ C, size_t cdoff, size_t sdoff, int nsplit,
         int ldc, int crevd,
         int M, int K, int epi,
         const float* __restrict__ biasf, const float* __restrict__ biasb,
         const float* __restrict__ resid, int ldr)
{
    constexpr int BN = 128;
    constexpr int TM = BM / 16;
    constexpr int NAc = (BM * BK) / 1024;
    constexpr int NBc = BK / 8;
    constexpr int ST = 3;
    __shared__ __align__(16) float As[ST][BK][BM + 4];
    __shared__ __align__(16) float Bs[ST][BK][BN + 8];

    const int s   = blockIdx.z % nsplit;
    const int dir = blockIdx.z / nsplit;
    const float* A    = (dir ? Ab : Af) + (size_t)s * K * ldm;
    const float* W    = (dir ? Wb : Wf) + (size_t)s * K * ldn;
    const float* bias = dir ? biasb : biasf;
    const int crev = crevd & -dir;
    const size_t cdo = (size_t)dir * cdoff + (size_t)s * sdoff;

    const int tid  = threadIdx.x;
    const int row0 = blockIdx.y * BM;
    const int col0 = blockIdx.x * BN;
    const int tx   = tid & 15;
    const int ty   = tid >> 4;

    u64t acc2[TM][4];
#pragma unroll
    for (int i = 0; i < TM; i++)
#pragma unroll
        for (int j = 0; j < 4; j++) acc2[i][j] = 0ull;

    auto issue = [&](int ki, int buf) {
        const int kb = ki * BK;
#pragma unroll
        for (int l = 0; l < NAc; l++) {
            int fi = tid + l * 256;
            int kk = fi / (BM / 4);
            int mc = fi % (BM / 4);
            uint32_t dst = smem_u32(&As[buf][kk][mc * 4]);
            const float* src = A + (size_t)(kb + kk) * ldm + row0 + mc * 4;
            CP_ASYNC16(dst, src);
        }
#pragma unroll
        for (int l = 0; l < NBc; l++) {
            int fi = tid + l * 256;
            int kk = fi >> 5, m = fi & 31;
            uint32_t dst = smem_u32(&Bs[buf][kk][(m >> 1) * 4 + (m & 1) * 64]);
            const float* src = W + (size_t)(kb + kk) * ldn + col0 + m * 4;
            CP_ASYNC16(dst, src);
        }
        CP_COMMIT();
    };

    const int nk = K / BK;
    issue(0, 0);
    if (nk > 1) issue(1, 1);

    for (int ki = 0; ki < nk; ki++) {
        if (ki + 1 < nk) { CP_WAIT1(); } else { CP_WAIT0(); }
        __syncthreads();
        if (ki + 2 < nk) issue(ki + 2, (ki + 2) % ST);
        const int cur = ki % ST;
#pragma unroll
        for (int kk = 0; kk < BK; kk++) {
            float a[TM];
#pragma unroll
            for (int i = 0; i < TM; i += 4)
                *reinterpret_cast<float4*>(&a[i]) =
                    *reinterpret_cast<const float4*>(&As[cur][kk][ty * TM + i]);
            u64t b2[4];
            {
                ulonglong2 bv0 = *reinterpret_cast<const ulonglong2*>(&Bs[cur][kk][tx * 4]);
                ulonglong2 bv1 = *reinterpret_cast<const ulonglong2*>(&Bs[cur][kk][64 + tx * 4]);
                b2[0] = bv0.x; b2[1] = bv0.y;
                b2[2] = bv1.x; b2[3] = bv1.y;
            }
#pragma unroll
            for (int i = 0; i < TM; i++) {
                u64t a2 = pack2(a[i], a[i]);
#pragma unroll
                for (int j = 0; j < 4; j++)
                    FFMA2(acc2[i][j], a2, b2[j], acc2[i][j]);
            }
        }
    }

#pragma unroll
    for (int i = 0; i < TM; i++) {
        int lr = row0 + ty * TM + i;
        int pr = crev ? (M - 1 - lr) : lr;
#pragma unroll
        for (int j = 0; j < 4; j++) {
            float v0, v1;
            unpack2(acc2[i][j], v0, v1);
            int c0 = col0 + tx * 8 + j * 2;
            if (epi == 1) {
                v0 = softplus_f(v0 + bias[c0]);
                v1 = softplus_f(v1 + bias[c0 + 1]);
            } else if (epi == 2) {
                v0 += resid[(size_t)pr * ldr + c0];
                v1 += resid[(size_t)pr * ldr + c0 + 1];
            } else if (epi == 3) {
                v0 += bias[c0];
                v1 += bias[c0 + 1];
            }
            C[cdo + (size_t)pr * ldc + c0]     = v0;
            C[cdo + (size_t)pr * ldc + c0 + 1] = v1;
        }
    }
}

// ---------------- out_reduce ----------------
__global__ void __launch_bounds__(256)
out_reduce(const float* __restrict__ x)
{
    int idx = blockIdx.x * blockDim.x + threadIdx.x;
    int c   = idx & (DM - 1);
    int t   = (idx >> 10) & (LSEQ - 1);
    int dir = idx >> 20;
    int pr  = dir ? (LSEQ - 1 - t) : t;
    float v = g_opart[dir][0][t][c] + g_opart[dir][1][t][c] + x[(size_t)pr * DM + c];
    g_cat[pr][dir * DM + c] = v;
}

// ---------------- conv + silu ----------------
__global__ void conv_silu_kernel(const float* __restrict__ cwf, const float* __restrict__ cbf,
                                 const float* __restrict__ cwb, const float* __restrict__ cbb)
{
    int idx = blockIdx.x * blockDim.x + threadIdx.x;
    int d   = idx & (DI - 1);
    int t   = (idx >> 11) & (LSEQ - 1);
    int dir = idx >> 21;
    const float* cw = dir ? cwb : cwf;
    const float* cb = dir ? cbb : cbf;
    float w0 = cw[d * 4 + 0], w1 = cw[d * 4 + 1], w2 = cw[d * 4 + 2], w3 = cw[d * 4 + 3];
    const float* xi = &g_xz[dir][0][d];
    float acc = cb[d];
    if (t >= 3) acc += w0 * xi[(t - 3) * (2 * DI)];
    if (t >= 2) acc += w1 * xi[(t - 2) * (2 * DI)];
    if (t >= 1) acc += w2 * xi[(t - 1) * (2 * DI)];
    acc += w3 * xi[t * (2 * DI)];
    g_u[dir][t][d] = acc * sigmoid_f(acc);
}

// ---------------- x-proj: 16-way split-K ----------------
__global__ void __launch_bounds__(256)
xproj_partial_kernel(const float* __restrict__ wf, const float* __restrict__ wb)
{
    const int chunk = blockIdx.x;
    const int mb    = blockIdx.y;
    const int dir   = blockIdx.z;
    const float* W  = dir ? wb : wf;
    const int row0  = mb * 32;
    const int kbase = chunk * 128;
    const int tid   = threadIdx.x;

    __shared__ __align__(16) float Us[32][36];
    __shared__ __align__(16) float Ws[32][100];

    const int tx = tid & 15;
    const int ty = tid >> 4;
    float acc[2][6];
#pragma unroll
    for (int i = 0; i < 2; i++)
#pragma unroll
        for (int j = 0; j < 6; j++) acc[i][j] = 0.f;

#pragma unroll
    for (int k0 = 0; k0 < 128; k0 += 32) {
        {
            int r  = tid >> 3;
            int kk = (tid & 7) << 2;
            float4 v = *reinterpret_cast<const float4*>(&g_u[dir][row0 + r][kbase + k0 + kk]);
            Us[kk + 0][r] = v.x; Us[kk + 1][r] = v.y;
            Us[kk + 2][r] = v.z; Us[kk + 3][r] = v.w;
        }
#pragma unroll
        for (int l = 0; l < 3; l++) {
            int fi = tid + l * 256;
            int n  = fi >> 3;
            int kk = (fi & 7) << 2;
            float4 v = *reinterpret_cast<const float4*>(&W[(size_t)n * DI + kbase + k0 + kk]);
            Ws[kk + 0][n] = v.x; Ws[kk + 1][n] = v.y;
            Ws[kk + 2][n] = v.z; Ws[kk + 3][n] = v.w;
        }
        __syncthreads();
#pragma unroll
        for (int kk = 0; kk < 32; kk++) {
            float a0 = Us[kk][ty * 2 + 0];
            float a1 = Us[kk][ty * 2 + 1];
#pragma unroll
            for (int j = 0; j < 6; j++) {
                float bv = Ws[kk][tx * 6 + j];
                acc[0][j] = fmaf(a0, bv, acc[0][j]);
                acc[1][j] = fmaf(a1, bv, acc[1][j]);
            }
        }
        __syncthreads();
    }
#pragma unroll
    for (int i = 0; i < 2; i++)
#pragma unroll
        for (int j = 0; j < 6; j++)
            g_xdbl_part[dir][chunk][row0 + ty * 2 + i][tx * 6 + j] = acc[i][j];
}

__global__ void xdbl_reduce_kernel()
{
    int idx = blockIdx.x * blockDim.x + threadIdx.x;
    int c   = idx % 96;
    int t   = (idx / 96) & (LSEQ - 1);
    int dir = idx / (96 * LSEQ);
    float s = 0.f;
#pragma unroll
    for (int ch = 0; ch < 16; ch++) s += g_xdbl_part[dir][ch][t][c];
    g_xdbl[dir][t][c] = s;
    if (c < DTR) g_xdT[dir][c][t] = s;
}

// ---------------- selective scan ----------------
__global__ void __launch_bounds__(128)
scan_kernel(const float* __restrict__ Alf, const float* __restrict__ Dpf,
            const float* __restrict__ Alb, const float* __restrict__ Dpb)
{
    int gid = blockIdx.x * 128 + threadIdx.x;
    int q   = gid & 3;
    int grp = gid >> 2;
    int dir = grp >> 11;
    int d   = grp & (DI - 1);

    const float* Alog = dir ? Alb : Alf;
    float dp = (dir ? Dpb : Dpf)[d];
    float Aa[4];
#pragma unroll
    for (int j = 0; j < 4; j++) Aa[j] = -expf(Alog[d * DS + q * 4 + j]);

    const float* dep = &g_delta[dir][0][d];
    const float* up  = &g_u[dir][0][d];
    const float* zp  = &g_xz[dir][0][DI + d];
    const float* bcp = &g_xdbl[dir][0][DTR + q * 4];
    float* ypT = &g_y2T[dir][d][0];

    float h0 = 0.f, h1 = 0.f, h2 = 0.f, h3 = 0.f;

    float dA[4], uA[4], zA[4]; float4 BA[4], CA[4];
    float dB[4], uB[4], zB[4]; float4 BB[4], CB[4];

#define LOADCH(t0, dv, uv, zv, Bv, Cv) do {                                   \
    _Pragma("unroll")                                                         \
    for (int i = 0; i < 4; i++) {                                             \
        dv[i] = dep[((t0) + i) * DI];                                         \
        uv[i] = up [((t0) + i) * DI];                                         \
        zv[i] = zp [((t0) + i) * (2 * DI)];                                   \
        Bv[i] = *reinterpret_cast<const float4*>(bcp + ((t0) + i) * 96);      \
        Cv[i] = *reinterpret_cast<const float4*>(bcp + ((t0) + i) * 96 + DS); \
    } } while (0)

#define COMPCH(t0, dv, uv, zv, Bv, Cv) do {                                   \
    float yout[4];                                                            \
    _Pragma("unroll")                                                         \
    for (int i = 0; i < 4; i++) {                                             \
        float dc = dv[i], uc = uv[i], zc = zv[i];                             \
        float4 Bc = Bv[i], Cc = Cv[i];                                        \
        float db = dc * uc;                                                   \
        float e0 = __expf(dc * Aa[0]);                                        \
        float e1 = __expf(dc * Aa[1]);                                        \
        float e2 = __expf(dc * Aa[2]);                                        \
        float e3 = __expf(dc * Aa[3]);                                        \
        h0 = fmaf(e0, h0, db * Bc.x);                                         \
        h1 = fmaf(e1, h1, db * Bc.y);                                         \
        h2 = fmaf(e2, h2, db * Bc.z);                                         \
        h3 = fmaf(e3, h3, db * Bc.w);                                         \
        float p = h0 * Cc.x + h1 * Cc.y + h2 * Cc.z + h3 * Cc.w;              \
        p += __shfl_xor_sync(0xffffffffu, p, 1);                              \
        p += __shfl_xor_sync(0xffffffffu, p, 2);                              \
        if (q == 0) yout[i] = (p + uc * dp) * zc * sigmoid_f(zc);             \
    }                                                                         \
    if (q == 0) {                                                             \
        float4 v; v.x = yout[0]; v.y = yout[1]; v.z = yout[2]; v.w = yout[3]; \
        *reinterpret_cast<float4*>(ypT + (t0)) = v;                           \
    } } while (0)

    LOADCH(0, dA, uA, zA, BA, CA);
    for (int c = 0; c < LSEQ / 4; c += 2) {
        if (c + 1 < LSEQ / 4) LOADCH((c + 1) * 4, dB, uB, zB, BB, CB);
        COMPCH(c * 4, dA, uA, zA, BA, CA);
        if (c + 2 < LSEQ / 4) LOADCH((c + 2) * 4, dA, uA, zA, BA, CA);
        COMPCH((c + 1) * 4, dB, uB, zB, BB, CB);
    }
#undef LOADCH
#undef COMPCH
}

// ---------------- layernorm fused with final-proj split-K reduce ----------------
__global__ void __launch_bounds__(256)
layernorm_kernel(const float* __restrict__ pbias,
                 const float* __restrict__ lw, const float* __restrict__ lb,
                 float* __restrict__ out)
{
    int row = blockIdx.x;
    float vr[4];
    float s = 0.f, s2 = 0.f;
#pragma unroll
    for (int l = 0; l < 4; l++) {
        int i = threadIdx.x + l * 256;
        float v = pbias[i]
                + g_fpart[0][row][i] + g_fpart[1][row][i]
                + g_fpart[2][row][i] + g_fpart[3][row][i];
        vr[l] = v;
        s += v; s2 += v * v;
    }
#pragma unroll
    for (int o = 16; o > 0; o >>= 1) {
        s  += __shfl_xor_sync(0xffffffffu, s,  o);
        s2 += __shfl_xor_sync(0xffffffffu, s2, o);
    }
    __shared__ float sm1[8], sm2[8];
    __shared__ float mu_s, rs_s;
    int w = threadIdx.x >> 5;
    if ((threadIdx.x & 31) == 0) { sm1[w] = s; sm2[w] = s2; }
    __syncthreads();
    if (threadIdx.x == 0) {
        float S = 0.f, S2 = 0.f;
#pragma unroll
        for (int i = 0; i < 8; i++) { S += sm1[i]; S2 += sm2[i]; }
        float mu  = S * (1.f / DM);
        float var = S2 * (1.f / DM) - mu * mu;
        mu_s = mu;
        rs_s = rsqrtf(var + 1e-5f);
    }
    __syncthreads();
    float mu = mu_s, rs = rs_s;
#pragma unroll
    for (int l = 0; l < 4; l++) {
        int i = threadIdx.x + l * 256;
        out[(size_t)row * DM + i] = (vr[l] - mu) * rs * lw[i] + lb[i];
    }
}

// ---------------- launch ----------------
extern "C" void kernel_launch(void* const* d_in, const int* in_sizes, int n_in,
                              void* d_out, int out_size)
{
    const float* x         = (const float*)d_in[0];
    const float* fw_in_w   = (const float*)d_in[1];
    const float* fw_conv_w = (const float*)d_in[2];
    const float* fw_conv_b = (const float*)d_in[3];
    const float* fw_xproj  = (const float*)d_in[4];
    const float* fw_dt_w   = (const float*)d_in[5];
    const float* fw_dt_b   = (const float*)d_in[6];
    const float* fw_Alog   = (const float*)d_in[7];
    const float* fw_Dp     = (const float*)d_in[8];
    const float* fw_out_w  = (const float*)d_in[9];
    const float* bw_in_w   = (const float*)d_in[10];
    const float* bw_conv_w = (const float*)d_in[11];
    const float* bw_conv_b = (const float*)d_in[12];
    const float* bw_xproj  = (const float*)d_in[13];
    const float* bw_dt_w   = (const float*)d_in[14];
    const float* bw_dt_b   = (const float*)d_in[15];
    const float* bw_Alog   = (const float*)d_in[16];
    const float* bw_Dp     = (const float*)d_in[17];
    const float* bw_out_w  = (const float*)d_in[18];
    const float* proj_w    = (const float*)d_in[19];
    const float* proj_b    = (const float*)d_in[20];
    const float* ln_w      = (const float*)d_in[21];
    const float* ln_b      = (const float*)d_in[22];
    float* out = (float*)d_out;

    float *xz, *del, *dtwT, *xdT, *y2T, *catT, *outwT, *pwT, *opart, *fpart;
    cudaGetSymbolAddress((void**)&xz,    g_xz);
    cudaGetSymbolAddress((void**)&del,   g_delta);
    cudaGetSymbolAddress((void**)&outwT, g_outwT);
    cudaGetSymbolAddress((void**)&pwT,   g_pwT);
    cudaGetSymbolAddress((void**)&dtwT,  g_dtwT);
    cudaGetSymbolAddress((void**)&xdT,   g_xdT);
    cudaGetSymbolAddress((void**)&y2T,   g_y2T);
    cudaGetSymbolAddress((void**)&catT,  g_catT);
    cudaGetSymbolAddress((void**)&opart, g_opart);
    cudaGetSymbolAddress((void**)&fpart, g_fpart);

    const size_t OUTW = (size_t)DI * DM;
    const size_t DTW = (size_t)DTR * DI;
    const size_t XDT = (size_t)DTR * LSEQ;
    const size_t Y2T = (size_t)DI * LSEQ;
    const size_t PLANE = (size_t)LSEQ * DM;

    // 0-2) prep + transposes (profiler anchors; in_proj lands at idx 3)
    transpose_all<<<6400, 256>>>(fw_out_w, bw_out_w, proj_w, fw_dt_w, bw_dt_w);
    prep_x_kernel<<<256, 256>>>(x);
    prep_w_kernel<<<2048, 256>>>(fw_in_w, bw_in_w);

    // 3) in_proj via bf16 mma (M=1024, N=4096, K=1024), fw+bw merged
    mma_inproj<<<dim3(32, 8, 2), 256>>>(xz);

    // 4) conv + silu -> u
    conv_silu_kernel<<<(2 * LSEQ * DI) / 256, 256>>>(fw_conv_w, fw_conv_b, bw_conv_w, bw_conv_b);

    // 5) x-proj (16-way split-K) -> x_dbl (+ k-major dt cols)
    dim3 gx(16, 32, 2);
    xproj_partial_kernel<<<gx, 256>>>(fw_xproj, bw_xproj);
    xdbl_reduce_kernel<<<(2 * LSEQ * 96) / 256, 256>>>();

    // 6) delta = softplus(dt @ dt_w^T + dt_b)  (M=1024, N=2048, K=64)
    sgemm_ca<128,32,2><<<dim3(16, 8, 2), 256>>>(
        xdT, xdT + XDT, LSEQ, dtwT, dtwT + DTW, DI,
        del, (size_t)LSEQ * DI, 0, 1, DI, 0,
        LSEQ, DTR, 1, fw_dt_b, bw_dt_b, nullptr, 0);

    // 7) selective scan -> y2^T
    scan_kernel<<<128, 128>>>(fw_Alog, fw_Dp, bw_Alog, bw_Dp);

    // 8) out_proj split-K2 -> opart
    sgemm_ca<128,32,2><<<dim3(8, 8, 4), 256>>>(
        y2T, y2T + Y2T, LSEQ, outwT, outwT + OUTW, DM,
        opart, 2 * PLANE, PLANE, 2, DM, 0,
        LSEQ, DI / 2, 0, nullptr, nullptr, nullptr, 0);

    // 9) reduce partials + residual -> cat
    out_reduce<<<(2 * LSEQ * DM) / 256, 256>>>(x);

    // 10) cat -> catT
    transpose_cat<<<2048, 256>>>();

    // 11) final proj split-K4 -> fpart
    sgemm_ca<128,32,2><<<dim3(8, 8, 4), 256>>>(
        catT, catT, LSEQ, pwT, pwT, DM,
        fpart, 0, PLANE, 4, DM, 0,
        LSEQ, 2 * DM / 4, 0, nullptr, nullptr, nullptr, 0);

    // 12) layernorm (fused split-K reduce + bias) -> out
    layernorm_kernel<<<LSEQ, 256>>>(proj_b, ln_w, ln_b, out);
}